// round 1
// baseline (speedup 1.0000x reference)
#include <cuda_runtime.h>
#include <cuda_bf16.h>
#include <stdint.h>

#define B_ 512
#define T_ 32
#define D_ 512
#define M_ 1024
#define N_ (B_*T_)          // 16384
#define EPS_ 1e-5f

// ---------------- scratch (static device globals; no allocation) ----------------
__device__ __align__(16) __nv_bfloat16 g_a_bf[N_*D_];
__device__ __align__(16) __nv_bfloat16 g_v_bf[N_*D_];
__device__ __align__(16) __nv_bfloat16 g_e_bf[M_*D_];
__device__ float g_an[N_];
__device__ float g_vn[N_];
__device__ float g_en[M_];
__device__ __align__(16) float         g_sd_a[N_*M_];
__device__ __align__(16) float         g_sd_v[N_*M_];
__device__ __align__(16) __nv_bfloat16 g_adj_a[N_*M_];
__device__ __align__(16) __nv_bfloat16 g_adj_v[N_*M_];
__device__ __align__(16) __nv_bfloat16 g_lph_a[N_*M_];
__device__ __align__(16) __nv_bfloat16 g_lph_v[N_*M_];
__device__ __align__(16) float         g_scode[2*T_*B_*B_];
__device__ float g_pmin[2*256];
__device__ float g_shift[2];
__device__ float g_rowloss[2*T_*B_];

// ---------------- reduction helpers ----------------
__device__ __forceinline__ float warpRedSum(float v){
  #pragma unroll
  for (int o=16;o>0;o>>=1) v += __shfl_xor_sync(0xffffffffu, v, o);
  return v;
}
__device__ __forceinline__ float warpRedMin(float v){
  #pragma unroll
  for (int o=16;o>0;o>>=1) v = fminf(v, __shfl_xor_sync(0xffffffffu, v, o));
  return v;
}
__device__ float blockSum(float v){
  __shared__ float sm[32]; __shared__ float res;
  int lane = threadIdx.x & 31, w = threadIdx.x >> 5, nw = blockDim.x >> 5;
  v = warpRedSum(v);
  if (!lane) sm[w] = v;
  __syncthreads();
  if (w == 0){
    float t = (lane < nw) ? sm[lane] : 0.f;
    t = warpRedSum(t);
    if (!lane) res = t;
  }
  __syncthreads();
  return res;
}
__device__ float blockMin(float v){
  __shared__ float sm[32]; __shared__ float res;
  int lane = threadIdx.x & 31, w = threadIdx.x >> 5, nw = blockDim.x >> 5;
  v = warpRedMin(v);
  if (!lane) sm[w] = v;
  __syncthreads();
  if (w == 0){
    float t = (lane < nw) ? sm[lane] : 3.4e38f;
    t = warpRedMin(t);
    if (!lane) res = t;
  }
  __syncthreads();
  return res;
}

// ---------------- small kernels ----------------
__global__ void k_cvt(const float* __restrict__ in, __nv_bfloat16* __restrict__ out, int n){
  int n4 = n >> 2;
  for (int i = blockIdx.x*blockDim.x + threadIdx.x; i < n4; i += gridDim.x*blockDim.x){
    float4 f = ((const float4*)in)[i];
    __nv_bfloat162* o = (__nv_bfloat162*)(out + 4*(size_t)i);
    o[0] = __floats2bfloat162_rn(f.x, f.y);
    o[1] = __floats2bfloat162_rn(f.z, f.w);
  }
}

__global__ void k_rownorm(const float* __restrict__ x, float* __restrict__ o, int d){
  const float* row = x + (size_t)blockIdx.x * d;
  float s = 0.f;
  for (int i = threadIdx.x; i < d; i += blockDim.x){ float t = row[i]; s = fmaf(t, t, s); }
  s = blockSum(s);
  if (threadIdx.x == 0) o[blockIdx.x] = s;
}

// ---------------- bf16 mma GEMM (NT: C[i,j] = sum_k A[i,k]*B[j,k]) ----------------
__device__ __forceinline__ void mma_bf16(float* c, const uint32_t* a, const uint32_t* b){
  asm volatile("mma.sync.aligned.m16n8k16.row.col.f32.bf16.bf16.f32 "
    "{%0,%1,%2,%3}, {%4,%5,%6,%7}, {%8,%9}, {%0,%1,%2,%3};"
    : "+f"(c[0]), "+f"(c[1]), "+f"(c[2]), "+f"(c[3])
    : "r"(a[0]), "r"(a[1]), "r"(a[2]), "r"(a[3]), "r"(b[0]), "r"(b[1]));
}

// EPI==0: C = sqrt(max(rn[row]+cn[col]-2*acc, 0))   (distance epilogue)
// EPI==1: C = acc                                   (plain store)
template<int EPI>
__global__ void __launch_bounds__(256)
k_gemm(const __nv_bfloat16* __restrict__ A, const __nv_bfloat16* __restrict__ Bm,
       float* __restrict__ C,
       int lda, int ldb, int ldc, int kdim,
       long sA, long sB, long sC,
       const float* __restrict__ rn, const float* __restrict__ cn)
{
  constexpr int BM=128, BN=128, BK=32, PAD=8;
  __shared__ __align__(16) __nv_bfloat16 As[2][BM][BK+PAD];
  __shared__ __align__(16) __nv_bfloat16 Bs[2][BN][BK+PAD];
  const int tid  = threadIdx.x;
  const int lane = tid & 31;
  const int warp = tid >> 5;
  const int wm = (warp >> 2) * 64;   // 2 warps in M
  const int wn = (warp &  3) * 32;   // 4 warps in N

  const __nv_bfloat16* Ab = A  + (long)blockIdx.z * sA + (long)blockIdx.y * BM * lda;
  const __nv_bfloat16* Bb = Bm + (long)blockIdx.z * sB + (long)blockIdx.x * BN * ldb;
  float* Cb = C + (long)blockIdx.z * sC;

  float acc[4][4][4];
  #pragma unroll
  for (int a=0;a<4;a++)
    #pragma unroll
    for (int b=0;b<4;b++)
      #pragma unroll
      for (int c=0;c<4;c++) acc[a][b][c]=0.f;

  const int lrow = tid >> 2;
  const int lc8  = (tid & 3) * 8;
  const int KT = kdim / BK;

  // prologue: stage 0
  {
    #pragma unroll
    for (int it=0; it<2; ++it){
      int r = lrow + it*64;
      unsigned sa = (unsigned)__cvta_generic_to_shared(&As[0][r][lc8]);
      asm volatile("cp.async.cg.shared.global [%0], [%1], 16;\n" :: "r"(sa), "l"(Ab + (long)r*lda + lc8));
      unsigned sb = (unsigned)__cvta_generic_to_shared(&Bs[0][r][lc8]);
      asm volatile("cp.async.cg.shared.global [%0], [%1], 16;\n" :: "r"(sb), "l"(Bb + (long)r*ldb + lc8));
    }
    asm volatile("cp.async.commit_group;\n");
  }

  const int fr = lane >> 2;
  const int fc = (lane & 3) * 2;

  for (int kt=0; kt<KT; ++kt){
    int buf = kt & 1;
    if (kt+1 < KT){
      int k0 = (kt+1)*BK; int nb = buf^1;
      #pragma unroll
      for (int it=0; it<2; ++it){
        int r = lrow + it*64;
        unsigned sa = (unsigned)__cvta_generic_to_shared(&As[nb][r][lc8]);
        asm volatile("cp.async.cg.shared.global [%0], [%1], 16;\n" :: "r"(sa), "l"(Ab + (long)r*lda + k0 + lc8));
        unsigned sb = (unsigned)__cvta_generic_to_shared(&Bs[nb][r][lc8]);
        asm volatile("cp.async.cg.shared.global [%0], [%1], 16;\n" :: "r"(sb), "l"(Bb + (long)r*ldb + k0 + lc8));
      }
      asm volatile("cp.async.commit_group;\n");
      asm volatile("cp.async.wait_group 1;\n");
    } else {
      asm volatile("cp.async.wait_group 0;\n");
    }
    __syncthreads();

    #pragma unroll
    for (int ks=0; ks<BK; ks+=16){
      uint32_t af[4][4], bfr[4][2];
      #pragma unroll
      for (int mi=0; mi<4; ++mi){
        int rbase = wm + mi*16 + fr;
        af[mi][0] = *(const uint32_t*)&As[buf][rbase  ][ks+fc];
        af[mi][1] = *(const uint32_t*)&As[buf][rbase+8][ks+fc];
        af[mi][2] = *(const uint32_t*)&As[buf][rbase  ][ks+fc+8];
        af[mi][3] = *(const uint32_t*)&As[buf][rbase+8][ks+fc+8];
      }
      #pragma unroll
      for (int ni=0; ni<4; ++ni){
        int nbase = wn + ni*8 + fr;
        bfr[ni][0] = *(const uint32_t*)&Bs[buf][nbase][ks+fc];
        bfr[ni][1] = *(const uint32_t*)&Bs[buf][nbase][ks+fc+8];
      }
      #pragma unroll
      for (int mi=0; mi<4; ++mi)
        #pragma unroll
        for (int ni=0; ni<4; ++ni)
          mma_bf16(acc[mi][ni], af[mi], bfr[ni]);
    }
    __syncthreads();
  }

  // epilogue
  #pragma unroll
  for (int mi=0; mi<4; ++mi){
    #pragma unroll
    for (int ni=0; ni<4; ++ni){
      int grow = blockIdx.y*BM + wm + mi*16 + fr;
      int gcol = blockIdx.x*BN + wn + ni*8 + fc;
      #pragma unroll
      for (int q=0; q<4; ++q){
        int rr = grow + ((q>=2) ? 8 : 0);
        int cc = gcol + (q & 1);
        float val = acc[mi][ni][q];
        if (EPI == 0){
          float d = fmaf(-2.f, val, rn[rr] + cn[cc]);
          Cb[(long)rr*ldc + cc] = sqrtf(fmaxf(d, 0.f));
        } else {
          Cb[(long)rr*ldc + cc] = val;
        }
      }
    }
  }
}

// ---------------- dual-temperature softmax over each row of sd ----------------
// adj = softmax(-2*sd) = e1^2 / sum(e1^2),  lph = log(softmax(-sd) + 1e-10)
__global__ void k_softmax(const float* __restrict__ sd,
                          __nv_bfloat16* __restrict__ adj,
                          __nv_bfloat16* __restrict__ lph){
  size_t base = (size_t)blockIdx.x * M_;
  int tid = threadIdx.x;              // 256 threads, 4 elems each
  float v[4];
  float vmin = 3.4e38f;
  #pragma unroll
  for (int i=0;i<4;i++){ v[i] = sd[base + tid + 256*i]; vmin = fminf(vmin, v[i]); }
  float rmin = blockMin(vmin);
  float e[4]; float s1=0.f, s2=0.f;
  #pragma unroll
  for (int i=0;i<4;i++){ e[i] = expf(rmin - v[i]); s1 += e[i]; s2 += e[i]*e[i]; }
  s1 = blockSum(s1);
  s2 = blockSum(s2);
  float i1 = 1.0f/s1, i2 = 1.0f/s2;
  #pragma unroll
  for (int i=0;i<4;i++){
    int idx = tid + 256*i;
    adj[base+idx] = __float2bfloat16(e[i]*e[i]*i2);
    lph[base+idx] = __float2bfloat16(logf(fmaf(e[i], i1, 1e-10f)));
  }
}

// ---------------- global min over Scode (two-stage, deterministic) ----------------
__global__ void k_pmin(const float* __restrict__ p, int n, float* __restrict__ o){
  float m = 3.4e38f;
  for (int i = blockIdx.x*blockDim.x + threadIdx.x; i < n; i += gridDim.x*blockDim.x)
    m = fminf(m, p[i]);
  m = blockMin(m);
  if (threadIdx.x == 0) o[blockIdx.x] = m;
}
__global__ void k_fmin(const float* __restrict__ p, float* __restrict__ o){
  float m = p[threadIdx.x];          // 256 partials, 256 threads
  m = blockMin(m);
  if (threadIdx.x == 0) *o = -m;     // shift = max(-Scode) = -min(Scode)
}

// ---------------- per-row loss term ----------------
__global__ void k_loss(const float* __restrict__ sc, const float* __restrict__ shift,
                       float* __restrict__ rl){
  int l = blockIdx.x >> 14;                 // which lcmcm (T*B = 16384)
  int r = blockIdx.x & 16383;
  int i = r & (B_-1);                       // diagonal index
  const float* row = sc + (size_t)blockIdx.x * B_;
  float s = shift[l];
  float sum = expf(row[threadIdx.x] + s) + expf(row[threadIdx.x + 256] + s);
  sum = blockSum(sum);
  if (threadIdx.x == 0){
    float denom = sum + EPS_;
    float diag  = expf(row[i] + s);
    rl[blockIdx.x] = -logf(diag / denom);
  }
}

// ---------------- final deterministic mean ----------------
__global__ void k_final(const float* __restrict__ rl, float* __restrict__ out){
  double s = 0.0;
  for (int i = threadIdx.x; i < 2*T_*B_; i += blockDim.x) s += (double)rl[i];
  #pragma unroll
  for (int o=16;o>0;o>>=1) s += __shfl_xor_sync(0xffffffffu, s, o);
  __shared__ double sm[32];
  int lane = threadIdx.x & 31, w = threadIdx.x >> 5;
  if (!lane) sm[w] = s;
  __syncthreads();
  if (threadIdx.x == 0){
    double t = 0.0;
    for (int i=0;i<8;i++) t += sm[i];
    out[0] = (float)(t / (double)(2*T_*B_));  // = 0.5*(mean1+mean2)
  }
}

// ---------------- launch ----------------
extern "C" void kernel_launch(void* const* d_in, const int* in_sizes, int n_in,
                              void* d_out, int out_size)
{
  const float* a = (const float*)d_in[0];
  const float* v = (const float*)d_in[1];
  const float* e = (const float*)d_in[2];
  float* out = (float*)d_out;

  __nv_bfloat16 *pa, *pv, *pe, *paa, *pav, *pla, *plv;
  float *pan, *pvn, *pen, *psa, *psv, *psc, *ppm, *psh, *prl;
  cudaGetSymbolAddress((void**)&pa,  g_a_bf);
  cudaGetSymbolAddress((void**)&pv,  g_v_bf);
  cudaGetSymbolAddress((void**)&pe,  g_e_bf);
  cudaGetSymbolAddress((void**)&pan, g_an);
  cudaGetSymbolAddress((void**)&pvn, g_vn);
  cudaGetSymbolAddress((void**)&pen, g_en);
  cudaGetSymbolAddress((void**)&psa, g_sd_a);
  cudaGetSymbolAddress((void**)&psv, g_sd_v);
  cudaGetSymbolAddress((void**)&paa, g_adj_a);
  cudaGetSymbolAddress((void**)&pav, g_adj_v);
  cudaGetSymbolAddress((void**)&pla, g_lph_a);
  cudaGetSymbolAddress((void**)&plv, g_lph_v);
  cudaGetSymbolAddress((void**)&psc, g_scode);
  cudaGetSymbolAddress((void**)&ppm, g_pmin);
  cudaGetSymbolAddress((void**)&psh, g_shift);
  cudaGetSymbolAddress((void**)&prl, g_rowloss);

  // 1) convert to bf16
  k_cvt<<<2048, 256>>>(a, pa, N_*D_);
  k_cvt<<<2048, 256>>>(v, pv, N_*D_);
  k_cvt<<<256,  256>>>(e, pe, M_*D_);

  // 2) row norms (fp32)
  k_rownorm<<<N_, 128>>>(a, pan, D_);
  k_rownorm<<<N_, 128>>>(v, pvn, D_);
  k_rownorm<<<M_, 128>>>(e, pen, D_);

  // 3) distance GEMMs with sqrt epilogue: sd = sqrt(max(|x|^2+|e|^2-2 x.e, 0))
  dim3 g1(M_/128, N_/128, 1);
  k_gemm<0><<<g1, 256>>>(pa, pe, psa, D_, D_, M_, D_, 0, 0, 0, pan, pen);
  k_gemm<0><<<g1, 256>>>(pv, pe, psv, D_, D_, M_, D_, 0, 0, 0, pvn, pen);

  // 4) dual-temperature softmax -> adj (bf16), logpH (bf16)
  k_softmax<<<N_, 256>>>(psa, paa, pla);
  k_softmax<<<N_, 256>>>(psv, pav, plv);

  // 5) Scode batched GEMMs over t: rows of flat arrays have stride T*M, batch offset t*M
  dim3 g2(B_/128, B_/128, T_);
  k_gemm<1><<<g2, 256>>>(paa, plv, psc,               T_*M_, T_*M_, B_, M_,
                         (long)M_, (long)M_, (long)B_*B_, nullptr, nullptr);
  k_gemm<1><<<g2, 256>>>(pav, pla, psc + (size_t)T_*B_*B_, T_*M_, T_*M_, B_, M_,
                         (long)M_, (long)M_, (long)B_*B_, nullptr, nullptr);

  // 6) global shifts s_l = -min(Scode_l)
  k_pmin<<<256, 256>>>(psc,                       T_*B_*B_, ppm);
  k_pmin<<<256, 256>>>(psc + (size_t)T_*B_*B_,    T_*B_*B_, ppm + 256);
  k_fmin<<<1, 256>>>(ppm,       psh + 0);
  k_fmin<<<1, 256>>>(ppm + 256, psh + 1);

  // 7) per-row loss terms, then deterministic mean
  k_loss<<<2*T_*B_, 256>>>(psc, psh, prl);
  k_final<<<1, 256>>>(prl, out);
}

// round 4
// speedup vs baseline: 1.5483x; 1.5483x over previous
#include <cuda_runtime.h>
#include <cuda_bf16.h>
#include <stdint.h>

#define B_ 512
#define T_ 32
#define D_ 512
#define M_ 1024
#define N_ (B_*T_)          // 16384
#define EPS_ 1e-5f

// ---------------- scratch (static device globals; no allocation) ----------------
__device__ __align__(16) __nv_bfloat16 g_a_bf[N_*D_];
__device__ __align__(16) __nv_bfloat16 g_v_bf[N_*D_];
__device__ __align__(16) __nv_bfloat16 g_e_bf[M_*D_];
__device__ float g_an[N_];
__device__ float g_vn[N_];
__device__ float g_en[M_];
__device__ __align__(16) __nv_bfloat16 g_sd_a[N_*M_];   // bf16 distances
__device__ __align__(16) __nv_bfloat16 g_sd_v[N_*M_];
__device__ __align__(16) __nv_bfloat16 g_adj_a[N_*M_];
__device__ __align__(16) __nv_bfloat16 g_adj_v[N_*M_];
__device__ float g_L_a[N_];                             // logsumexp(-sd) per row
__device__ float g_L_v[N_];
__device__ __align__(16) float g_scode[2*T_*B_*B_];
__device__ unsigned g_minkey[2];
__device__ float g_shift[2];
__device__ float g_rowloss[2*T_*B_];

// ---------------- reduction helpers ----------------
__device__ __forceinline__ float warpRedSum(float v){
  #pragma unroll
  for (int o=16;o>0;o>>=1) v += __shfl_xor_sync(0xffffffffu, v, o);
  return v;
}
__device__ __forceinline__ float warpRedMin(float v){
  #pragma unroll
  for (int o=16;o>0;o>>=1) v = fminf(v, __shfl_xor_sync(0xffffffffu, v, o));
  return v;
}
__device__ float blockSum(float v){
  __shared__ float sm[32]; __shared__ float res;
  int lane = threadIdx.x & 31, w = threadIdx.x >> 5, nw = blockDim.x >> 5;
  v = warpRedSum(v);
  if (!lane) sm[w] = v;
  __syncthreads();
  if (w == 0){
    float t = (lane < nw) ? sm[lane] : 0.f;
    t = warpRedSum(t);
    if (!lane) res = t;
  }
  __syncthreads();
  return res;
}
__device__ float blockMin(float v){
  __shared__ float sm[32]; __shared__ float res;
  int lane = threadIdx.x & 31, w = threadIdx.x >> 5, nw = blockDim.x >> 5;
  v = warpRedMin(v);
  if (!lane) sm[w] = v;
  __syncthreads();
  if (w == 0){
    float t = (lane < nw) ? sm[lane] : 3.4e38f;
    t = warpRedMin(t);
    if (!lane) res = t;
  }
  __syncthreads();
  return res;
}

__device__ __forceinline__ unsigned fkey(float f){
  unsigned u = __float_as_uint(f);
  return (u & 0x80000000u) ? ~u : (u | 0x80000000u);
}

// ---------------- fused fp32->bf16 convert + row sq-norm ----------------
__global__ void k_prep(const float* __restrict__ x, __nv_bfloat16* __restrict__ xb,
                       float* __restrict__ nrm){
  int row = blockIdx.x;
  const float4* src = (const float4*)(x + (size_t)row * D_);
  float4 f = src[threadIdx.x];
  float s = f.x*f.x + f.y*f.y + f.z*f.z + f.w*f.w;
  s = blockSum(s);
  __nv_bfloat162* dst = (__nv_bfloat162*)(xb + (size_t)row * D_);
  dst[threadIdx.x*2]   = __floats2bfloat162_rn(f.x, f.y);
  dst[threadIdx.x*2+1] = __floats2bfloat162_rn(f.z, f.w);
  if (threadIdx.x == 0) nrm[row] = s;
}

// ---------------- HMMA GEMM: C[i,j] = sum_k A[i,k]*B[j,k]  (NT) ----------------
// CTA tile 128x256, warp tile 64x64 (2x4 warps), BK=64, 3-stage cp.async,
// swizzled smem + ldmatrix.x4.
// EPI 0: sd = bf16(sqrt(max(rn[i]+cn[j]-2acc,0)))
// EPI 1: scode = -acc - L[j]  (fp32) + deterministic global-min via atomicMin key
__device__ __forceinline__ void cpa16(uint32_t s, const void* g){
  asm volatile("cp.async.cg.shared.global [%0], [%1], 16;" :: "r"(s), "l"(g));
}
__device__ __forceinline__ void ldmx4(uint32_t* r, uint32_t a){
  asm volatile("ldmatrix.sync.aligned.m8n8.x4.shared.b16 {%0,%1,%2,%3}, [%4];"
    : "=r"(r[0]), "=r"(r[1]), "=r"(r[2]), "=r"(r[3]) : "r"(a));
}
__device__ __forceinline__ void mma_bf16(float* c, const uint32_t* a, uint32_t b0, uint32_t b1){
  asm volatile("mma.sync.aligned.m16n8k16.row.col.f32.bf16.bf16.f32 "
    "{%0,%1,%2,%3}, {%4,%5,%6,%7}, {%8,%9}, {%0,%1,%2,%3};"
    : "+f"(c[0]), "+f"(c[1]), "+f"(c[2]), "+f"(c[3])
    : "r"(a[0]), "r"(a[1]), "r"(a[2]), "r"(a[3]), "r"(b0), "r"(b1));
}

#define GBM 128
#define GBN 256
#define GBK 64
#define ABYTES (GBM*128)
#define BBYTES (GBN*128)
#define STG (ABYTES+BBYTES)
#define SMEM_DYN (3*STG)

template<int EPI>
__global__ void __launch_bounds__(256, 1)
k_mma(const __nv_bfloat16* __restrict__ A, const __nv_bfloat16* __restrict__ Bm,
      void* __restrict__ Cv, int lda, int ldb, int ldc, int kdim,
      long sA, long sB, long sC,
      const float* __restrict__ rn, const float* __restrict__ cn,
      unsigned* __restrict__ minkey)
{
  extern __shared__ char dsm[];
  uint32_t sbase = (uint32_t)__cvta_generic_to_shared(dsm);
  const int tid = threadIdx.x;
  const int lane = tid & 31, warp = tid >> 5;
  const int wm = (warp >> 2) * 64, wn = (warp & 3) * 64;

  const long ldab = (long)lda*2, ldbb = (long)ldb*2;
  const char* Ab = (const char*)(A + (long)blockIdx.z*sA) + (long)blockIdx.y * GBM * ldab;
  const char* Bb = (const char*)(Bm + (long)blockIdx.z*sB) + (long)blockIdx.x * GBN * ldbb;
  const int KT = kdim / GBK;

  auto load_chunk = [&](int ck, int s){
    uint32_t dA = sbase + (uint32_t)s * STG;
    uint32_t dB = dA + ABYTES;
    long koff = (long)ck * 128;
    #pragma unroll
    for (int i=0;i<4;i++){                 // A: 1024 x 16B chunks
      int idx = tid + (i<<8); int r = idx >> 3, c = idx & 7;
      uint32_t off = (uint32_t)(r*128 + ((c ^ (r&7))<<4));
      cpa16(dA + off, Ab + (long)r*ldab + koff + c*16);
    }
    #pragma unroll
    for (int i=0;i<8;i++){                 // B: 2048 x 16B chunks
      int idx = tid + (i<<8); int r = idx >> 3, c = idx & 7;
      uint32_t off = (uint32_t)(r*128 + ((c ^ (r&7))<<4));
      cpa16(dB + off, Bb + (long)r*ldbb + koff + c*16);
    }
  };

  load_chunk(0,0); asm volatile("cp.async.commit_group;");
  load_chunk(1,1); asm volatile("cp.async.commit_group;");

  float acc[4][8][4];
  #pragma unroll
  for (int a=0;a<4;a++)
    #pragma unroll
    for (int b=0;b<8;b++)
      #pragma unroll
      for (int c=0;c<4;c++) acc[a][b][c]=0.f;

  for (int kt = 0; kt < KT; ++kt){
    if (kt+2 < KT) load_chunk(kt+2, (kt+2)%3);
    asm volatile("cp.async.commit_group;");
    asm volatile("cp.async.wait_group 2;");
    __syncthreads();
    uint32_t aB = sbase + (uint32_t)(kt%3) * STG;
    uint32_t bB = aB + ABYTES;
    #pragma unroll
    for (int ks=0; ks<4; ++ks){
      uint32_t af[4][4], bfr[4][4];
      #pragma unroll
      for (int mi=0; mi<4; ++mi){
        int row = wm + mi*16 + (lane & 15);
        int ch  = 2*ks + (lane >> 4);
        ldmx4(af[mi], aB + (uint32_t)(row*128 + ((ch ^ (row&7))<<4)));
      }
      #pragma unroll
      for (int p=0; p<4; ++p){
        int row = wn + p*16 + ((lane>>4)<<3) + (lane&7);
        int ch  = 2*ks + ((lane>>3)&1);
        ldmx4(bfr[p], bB + (uint32_t)(row*128 + ((ch ^ (row&7))<<4)));
      }
      #pragma unroll
      for (int mi=0; mi<4; ++mi)
        #pragma unroll
        for (int ni=0; ni<8; ++ni){
          const uint32_t* bp = bfr[ni>>1];
          uint32_t b0 = (ni&1) ? bp[2] : bp[0];
          uint32_t b1 = (ni&1) ? bp[3] : bp[1];
          mma_bf16(acc[mi][ni], af[mi], b0, b1);
        }
    }
    __syncthreads();
  }

  // ---------------- epilogue ----------------
  const int tr = lane >> 2;
  const int tc = (lane & 3) * 2;
  if (EPI == 0){
    __nv_bfloat16* Cb = (__nv_bfloat16*)Cv;
    #pragma unroll
    for (int mi=0; mi<4; ++mi){
      int r0 = blockIdx.y*GBM + wm + mi*16 + tr;
      float rn0 = rn[r0], rn1 = rn[r0+8];
      #pragma unroll
      for (int ni=0; ni<8; ++ni){
        int col = blockIdx.x*GBN + wn + ni*8 + tc;
        float c0 = cn[col], c1 = cn[col+1];
        float* a = acc[mi][ni];
        __nv_bfloat162 o0 = __floats2bfloat162_rn(
            sqrtf(fmaxf(fmaf(-2.f, a[0], rn0 + c0), 0.f)),
            sqrtf(fmaxf(fmaf(-2.f, a[1], rn0 + c1), 0.f)));
        __nv_bfloat162 o1 = __floats2bfloat162_rn(
            sqrtf(fmaxf(fmaf(-2.f, a[2], rn1 + c0), 0.f)),
            sqrtf(fmaxf(fmaf(-2.f, a[3], rn1 + c1), 0.f)));
        *(__nv_bfloat162*)&Cb[(long)r0*ldc + col] = o0;
        *(__nv_bfloat162*)&Cb[(long)(r0+8)*ldc + col] = o1;
      }
    }
  } else {
    float* Cb = (float*)Cv + (long)blockIdx.z * sC;
    float tmin = 3.4e38f;
    #pragma unroll
    for (int mi=0; mi<4; ++mi){
      int r0 = blockIdx.y*GBM + wm + mi*16 + tr;
      #pragma unroll
      for (int ni=0; ni<8; ++ni){
        int col = blockIdx.x*GBN + wn + ni*8 + tc;
        float L0 = cn[(long)col*T_ + blockIdx.z];
        float L1 = cn[(long)(col+1)*T_ + blockIdx.z];
        float* a = acc[mi][ni];
        float v0 = -a[0]-L0, v1 = -a[1]-L1, v2 = -a[2]-L0, v3 = -a[3]-L1;
        tmin = fminf(tmin, fminf(fminf(v0,v1), fminf(v2,v3)));
        float2 p0; p0.x=v0; p0.y=v1;
        float2 p1; p1.x=v2; p1.y=v3;
        *(float2*)&Cb[(long)r0*ldc + col] = p0;
        *(float2*)&Cb[(long)(r0+8)*ldc + col] = p1;
      }
    }
    tmin = warpRedMin(tmin);
    float* red = (float*)dsm;
    if (!lane) red[warp] = tmin;
    __syncthreads();
    if (tid == 0){
      float m = red[0];
      #pragma unroll
      for (int w=1; w<8; w++) m = fminf(m, red[w]);
      atomicMin(minkey, fkey(m));
    }
  }
}

// ---------------- softmax: adj = softmax(-2 sd) bf16, L = logsumexp(-sd) ----------------
__global__ void k_softmax2(const __nv_bfloat16* __restrict__ sd,
                           __nv_bfloat16* __restrict__ adj,
                           float* __restrict__ L){
  size_t base = (size_t)blockIdx.x * M_;
  int tid = threadIdx.x;              // 256 threads x 4 contiguous elems
  uint2 pk = *(const uint2*)(sd + base + tid*4);
  __nv_bfloat162 p0 = *(__nv_bfloat162*)&pk.x;
  __nv_bfloat162 p1 = *(__nv_bfloat162*)&pk.y;
  float v[4] = { __low2float(p0), __high2float(p0), __low2float(p1), __high2float(p1) };
  float vmin = fminf(fminf(v[0],v[1]), fminf(v[2],v[3]));
  float rmin = blockMin(vmin);
  float e[4]; float s1=0.f, s2=0.f;
  #pragma unroll
  for (int i=0;i<4;i++){ e[i] = expf(rmin - v[i]); s1 += e[i]; s2 += e[i]*e[i]; }
  s1 = blockSum(s1);
  s2 = blockSum(s2);
  float i2 = 1.0f/s2;
  uint2 out;
  __nv_bfloat162 a0 = __floats2bfloat162_rn(e[0]*e[0]*i2, e[1]*e[1]*i2);
  __nv_bfloat162 a1 = __floats2bfloat162_rn(e[2]*e[2]*i2, e[3]*e[3]*i2);
  out.x = *(unsigned*)&a0; out.y = *(unsigned*)&a1;
  *(uint2*)(adj + base + tid*4) = out;
  if (tid == 0) L[blockIdx.x] = logf(s1) - rmin;
}

// ---------------- min-key init / decode ----------------
__global__ void k_initmin(unsigned* mk){ if (threadIdx.x < 2) mk[threadIdx.x] = 0xFFFFFFFFu; }
__global__ void k_fmin2(const unsigned* mk, float* shift){
  if (threadIdx.x < 2){
    unsigned k = mk[threadIdx.x];
    float f = (k & 0x80000000u) ? __uint_as_float(k ^ 0x80000000u) : __uint_as_float(~k);
    shift[threadIdx.x] = -f;    // shift = max(-Scode) = -min(Scode)
  }
}

// ---------------- per-row loss term ----------------
__global__ void k_loss(const float* __restrict__ sc, const float* __restrict__ shift,
                       float* __restrict__ rl){
  int l = blockIdx.x >> 14;
  int r = blockIdx.x & 16383;
  int i = r & (B_-1);
  const float* row = sc + (size_t)blockIdx.x * B_;
  float s = shift[l];
  float sum = expf(row[threadIdx.x] + s) + expf(row[threadIdx.x + 256] + s);
  sum = blockSum(sum);
  if (threadIdx.x == 0){
    float denom = sum + EPS_;
    float diag  = expf(row[i] + s);
    rl[blockIdx.x] = -logf(diag / denom);
  }
}

// ---------------- final deterministic mean ----------------
__global__ void k_final(const float* __restrict__ rl, float* __restrict__ out){
  double s = 0.0;
  for (int i = threadIdx.x; i < 2*T_*B_; i += blockDim.x) s += (double)rl[i];
  #pragma unroll
  for (int o=16;o>0;o>>=1) s += __shfl_xor_sync(0xffffffffu, s, o);
  __shared__ double sm[32];
  int lane = threadIdx.x & 31, w = threadIdx.x >> 5;
  if (!lane) sm[w] = s;
  __syncthreads();
  if (threadIdx.x == 0){
    double t = 0.0;
    for (int i=0;i<8;i++) t += sm[i];
    out[0] = (float)(t / (double)(2*T_*B_));
  }
}

// ---------------- launch ----------------
extern "C" void kernel_launch(void* const* d_in, const int* in_sizes, int n_in,
                              void* d_out, int out_size)
{
  const float* a = (const float*)d_in[0];
  const float* v = (const float*)d_in[1];
  const float* e = (const float*)d_in[2];
  float* out = (float*)d_out;

  __nv_bfloat16 *pa, *pv, *pe, *psa, *psv, *paa, *pav;
  float *pan, *pvn, *pen, *pLa, *pLv, *psc, *psh, *prl;
  unsigned* pmk;
  cudaGetSymbolAddress((void**)&pa,  g_a_bf);
  cudaGetSymbolAddress((void**)&pv,  g_v_bf);
  cudaGetSymbolAddress((void**)&pe,  g_e_bf);
  cudaGetSymbolAddress((void**)&pan, g_an);
  cudaGetSymbolAddress((void**)&pvn, g_vn);
  cudaGetSymbolAddress((void**)&pen, g_en);
  cudaGetSymbolAddress((void**)&psa, g_sd_a);
  cudaGetSymbolAddress((void**)&psv, g_sd_v);
  cudaGetSymbolAddress((void**)&paa, g_adj_a);
  cudaGetSymbolAddress((void**)&pav, g_adj_v);
  cudaGetSymbolAddress((void**)&pLa, g_L_a);
  cudaGetSymbolAddress((void**)&pLv, g_L_v);
  cudaGetSymbolAddress((void**)&psc, g_scode);
  cudaGetSymbolAddress((void**)&pmk, g_minkey);
  cudaGetSymbolAddress((void**)&psh, g_shift);
  cudaGetSymbolAddress((void**)&prl, g_rowloss);

  cudaFuncSetAttribute(k_mma<0>, cudaFuncAttributeMaxDynamicSharedMemorySize, SMEM_DYN);
  cudaFuncSetAttribute(k_mma<1>, cudaFuncAttributeMaxDynamicSharedMemorySize, SMEM_DYN);

  k_initmin<<<1, 32>>>(pmk);

  // 1) fused convert + row sq-norms
  k_prep<<<N_, 128>>>(a, pa, pan);
  k_prep<<<N_, 128>>>(v, pv, pvn);
  k_prep<<<M_, 128>>>(e, pe, pen);

  // 2) distance GEMMs -> sd bf16
  dim3 g1(M_/GBN, N_/GBM, 1);
  k_mma<0><<<g1, 256, SMEM_DYN>>>(pa, pe, psa, D_, D_, M_, D_, 0, 0, 0, pan, pen, nullptr);
  k_mma<0><<<g1, 256, SMEM_DYN>>>(pv, pe, psv, D_, D_, M_, D_, 0, 0, 0, pvn, pen, nullptr);

  // 3) adj = softmax(-2 sd) bf16, L = logsumexp(-sd)
  k_softmax2<<<N_, 256>>>(psa, paa, pLa);
  k_softmax2<<<N_, 256>>>(psv, pav, pLv);

  // 4) Scode = -adj . sd^T - L[j]  (batched over t; rows stride T*M, offset t*M)
  dim3 g2(B_/GBN, B_/GBM, T_);
  k_mma<1><<<g2, 256, SMEM_DYN>>>(paa, psv, psc, T_*M_, T_*M_, B_, M_,
                                  (long)M_, (long)M_, (long)B_*B_, nullptr, pLv, pmk);
  k_mma<1><<<g2, 256, SMEM_DYN>>>(pav, psa, (float*)psc + (size_t)T_*B_*B_,
                                  T_*M_, T_*M_, B_, M_,
                                  (long)M_, (long)M_, (long)B_*B_, nullptr, pLa, pmk+1);

  // 5) shifts from deterministic min-keys
  k_fmin2<<<1, 32>>>(pmk, psh);

  // 6) per-row loss, deterministic mean
  k_loss<<<2*T_*B_, 256>>>(psc, psh, prl);
  k_final<<<1, 256>>>(prl, out);
}